// round 13
// baseline (speedup 1.0000x reference)
#include <cuda_runtime.h>
#include <math.h>

#define BATCH 8
#define NPTS  2048
#define NJ    21
#define NWGT  778
#define TOTAL (BATCH*NPTS)

// ---------------- device scratch ----------------
__device__ float4 g_q4[TOTAL];          // gen RAW: x,y,z,|q|^2
__device__ unsigned int g_qbits[TOTAL]; // gen joint-mask bits
__device__ int    g_label[TOTAL];       // argmin segment label per (b,m)
__device__ float4 g_tsorted[TOTAL];     // target sorted by label, SCALED: -2x,-2y,-2z,|t|^2
__device__ int    g_offs[BATCH*(NJ+1)];
__device__ float  g_cham1, g_cham2;
__device__ float  g_j1[NJ], g_j2[NJ];

__constant__ float c_ranges[NJ*6] = {
  -1.57f,1.57f, -1.57f,1.57f, -1.57f,1.57f,
  -1.05f,1.05f, 0.f,0.f, -0.79f,0.26f,
  -0.52f,0.52f, 0.f,0.f, -0.35f,0.79f,
  -0.26f,0.26f, 0.f,0.f, 0.f,0.f,
  -1.05f,0.f,   0.f,0.f, 0.f,0.f,
   0.f,0.f,     0.f,0.f, 0.f,0.f,
  -1.05f,0.26f, 0.f,0.f, -0.52f,0.26f,
  -0.52f,0.f,   0.f,0.f, 0.f,0.f,
  -0.52f,0.f,   0.f,0.f, 0.f,0.f,
   0.f,0.f,     0.f,0.f, 0.f,0.f,
  -1.05f,0.26f, 0.f,0.f, -0.52f,0.26f,
  -0.52f,0.f,   0.f,0.f, 0.f,0.f,
  -0.52f,0.f,   0.f,0.f, 0.f,0.f,
   0.f,0.f,     0.f,0.f, 0.f,0.f,
  -1.05f,0.26f, 0.f,0.f, -0.52f,0.26f,
  -0.52f,0.f,   0.f,0.f, 0.f,0.f,
  -0.52f,0.f,   0.f,0.f, 0.f,0.f,
   0.f,0.f,     0.f,0.f, 0.f,0.f,
  -1.05f,0.26f, 0.f,0.f, -0.52f,0.26f,
  -0.52f,0.f,   0.f,0.f, 0.f,0.f,
  -0.52f,0.f,   0.f,0.f, 0.f,0.f
};

// ---- K1: pack gen (norm + bits) + labels; block 0 also zeroes accumulators ----
__global__ void __launch_bounds__(256) k_pack_label(
        const float* __restrict__ gen, const int* __restrict__ idxs,
        const float* __restrict__ seg, const float* __restrict__ bw) {
    __shared__ float sl[256*NJ];
    __shared__ unsigned int swb[NWGT];
    int t = threadIdx.x, blk = blockIdx.x;
    int gid = blk*256 + t;
    if (blk == 0) {
        if (t < NJ) { g_j1[t] = 0.f; g_j2[t] = 0.f; }
        if (t == 0) { g_cham1 = 0.f; g_cham2 = 0.f; }
    }
    // per-block wbits table (coalesced along vertex dim)
    for (int v = t; v < NWGT; v += 256) {
        unsigned int bits = 0;
#pragma unroll
        for (int i = 0; i < NJ; i++)
            bits |= (bw[i*NWGT + v] > 0.15f) ? (1u << i) : 0u;
        swb[v] = bits;
    }
    // coalesced stage of this block's 256 points' logits
    const float* segb = seg + (size_t)blk*256*NJ;
    for (int i = t; i < 256*NJ; i += 256) sl[i] = segb[i];
    float x = gen[3*gid], y = gen[3*gid+1], z = gen[3*gid+2];
    float4 q; q.x = x; q.y = y; q.z = z; q.w = x*x + y*y + z*z;
    g_q4[gid] = q;
    __syncthreads();
    g_qbits[gid] = swb[idxs[gid]];
    const float* s = &sl[t*NJ];
    float best = s[0]; int bi = 0;
#pragma unroll
    for (int k = 1; k < NJ; k++) {
        float v = s[k];
        if (v < best) { best = v; bi = k; }
    }
    g_label[gid] = bi;
}

// ---- K2: per-batch counting sort; store pre-scaled (-2x,-2y,-2z,|t|^2) ----
__global__ void __launch_bounds__(512) k_sort(const float* __restrict__ tpc) {
    __shared__ int hist[NJ];
    __shared__ int cur[NJ];
    __shared__ int labs[NPTS];
    int t = threadIdx.x, b = blockIdx.x;
    if (t < NJ) hist[t] = 0;
    __syncthreads();
    int base = b << 11;
#pragma unroll
    for (int k = 0; k < 4; k++) {
        int i = t + 512*k;
        int lab = g_label[base + i];
        labs[i] = lab;
        atomicAdd(&hist[lab], 1);
    }
    __syncthreads();
    if (t == 0) {
        int run = 0;
        for (int j = 0; j < NJ; j++) {
            g_offs[b*(NJ+1) + j] = run;
            cur[j] = run;
            run += hist[j];
        }
        g_offs[b*(NJ+1) + NJ] = run;
    }
    __syncthreads();
#pragma unroll
    for (int k = 0; k < 4; k++) {
        int i = t + 512*k;
        int lab = labs[i];
        int pos = atomicAdd(&cur[lab], 1);
        int gi = base + i;
        float x = tpc[3*gi], y = tpc[3*gi+1], z = tpc[3*gi+2];
        float4 v;
        v.x = -2.f*x; v.y = -2.f*y; v.z = -2.f*z;
        v.w = x*x + y*y + z*z;
        g_tsorted[base + pos] = v;
    }
}

// ---- K3: FUSED main pass, 256 threads/block. Blocks [0,256): row; [256,512): col.
// Per warp: 8 queries (2 per lane ql=lane&3), oct=lane>>2 splits ranges 8 ways.
struct RowS { float4 sT[NPTS]; int soff[NJ+1]; float sj[NJ]; float scham; };
struct ColS { float4 sQ[NPTS]; unsigned int sB[NPTS]; float sj[NJ]; float scham; };
union MainS { RowS r; ColS c; };

__global__ void __launch_bounds__(256) k_main(const float* __restrict__ tpc) {
    __shared__ MainS sm;
    int t = threadIdx.x;
    int warp = t >> 5, lane = t & 31;
    int oct = lane >> 2, ql = lane & 3;

    if (blockIdx.x < 256) {
        // ================= ROW =================
        int b = blockIdx.x >> 5;            // 32 blocks per batch
        int qblk = blockIdx.x & 31;         // 64 queries per block
        for (int i = t; i < NPTS; i += 256) sm.r.sT[i] = g_tsorted[(b << 11) + i];
        if (t < NJ+1) sm.r.soff[t] = g_offs[b*(NJ+1) + t];
        if (t < NJ) sm.r.sj[t] = 0.f;
        if (t == 0) sm.r.scham = 0.f;
        __syncthreads();

        int qbase = (b << 11) + qblk*64 + warp*8;
        float4 qa = g_q4[qbase + ql];
        float4 qb = g_q4[qbase + 4 + ql];
        unsigned int bits_a = g_qbits[qbase + ql];
        unsigned int bits_b = g_qbits[qbase + 4 + ql];
        float gmall_a = 1e30f, gmall_b = 1e30f;

        for (int grp = 0; grp < NJ; grp++) {
            int s = sm.r.soff[grp], e = sm.r.soff[grp+1];
            int hlen = (e - s + 7) >> 3;
            int m0 = s + oct*hlen;
            int mend = min(m0 + hlen, e);
            float gma = 1e30f, gmb = 1e30f;
#pragma unroll 4
            for (int m = m0; m < mend; m++) {
                float4 tp = sm.r.sT[m];                   // pre-scaled -2
                float va = fmaf(qa.x, tp.x, tp.w);
                va = fmaf(qa.y, tp.y, va);
                va = fmaf(qa.z, tp.z, va);
                float vb = fmaf(qb.x, tp.x, tp.w);
                vb = fmaf(qb.y, tp.y, vb);
                vb = fmaf(qb.z, tp.z, vb);
                gma = fminf(gma, va);
                gmb = fminf(gmb, vb);
            }
            gma = fminf(gma, __shfl_xor_sync(0xffffffffu, gma, 4));
            gma = fminf(gma, __shfl_xor_sync(0xffffffffu, gma, 8));
            gma = fminf(gma, __shfl_xor_sync(0xffffffffu, gma, 16));
            gmb = fminf(gmb, __shfl_xor_sync(0xffffffffu, gmb, 4));
            gmb = fminf(gmb, __shfl_xor_sync(0xffffffffu, gmb, 8));
            gmb = fminf(gmb, __shfl_xor_sync(0xffffffffu, gmb, 16));
            gmall_a = fminf(gmall_a, gma);
            gmall_b = fminf(gmall_b, gmb);
            if (oct == 0 && ((bits_a >> grp) & 1u)) {
                float d = sqrtf(fmaxf(gma + qa.w, 0.f));
                if (d < 10.f) atomicAdd(&sm.r.sj[grp], d);
            }
            if (oct == 1 && ((bits_b >> grp) & 1u)) {
                float d = sqrtf(fmaxf(gmb + qb.w, 0.f));
                if (d < 10.f) atomicAdd(&sm.r.sj[grp], d);
            }
        }
        if (oct == 0) atomicAdd(&sm.r.scham, sqrtf(fmaxf(gmall_a + qa.w, 0.f)));
        if (oct == 1) atomicAdd(&sm.r.scham, sqrtf(fmaxf(gmall_b + qb.w, 0.f)));
        __syncthreads();
        if (t < NJ) atomicAdd(&g_j1[t], sm.r.sj[t]);
        if (t == 0) atomicAdd(&g_cham1, sm.r.scham);
    } else {
        // ================= COL =================
        int blk = blockIdx.x - 256;
        int b = blk >> 5;
        int mblk = blk & 31;
        for (int i = t; i < NPTS; i += 256) {
            float4 v = g_q4[(b << 11) + i];
            v.x *= -2.f; v.y *= -2.f; v.z *= -2.f;    // scale into tile
            sm.c.sQ[i] = v;
            sm.c.sB[i] = g_qbits[(b << 11) + i];
        }
        if (t < NJ) sm.c.sj[t] = 0.f;
        if (t == 0) sm.c.scham = 0.f;
        __syncthreads();

        int mbase = (b << 11) + mblk*64 + warp*8;
        int gia = mbase + ql, gib = mbase + 4 + ql;
        float tax = tpc[3*gia], tay = tpc[3*gia+1], taz = tpc[3*gia+2];
        float tbx = tpc[3*gib], tby = tpc[3*gib+1], tbz = tpc[3*gib+2];
        float tan2 = tax*tax + tay*tay + taz*taz;
        float tbn2 = tbx*tbx + tby*tby + tbz*tbz;
        int pa = g_label[gia], pb = g_label[gib];
        unsigned int maska = 1u << pa, maskb = 1u << pb;
        float gmina = 1e30f, gminb = 1e30f, pmina = 1e30f, pminb = 1e30f;
        int n0 = oct * (NPTS/8);

#pragma unroll 4
        for (int i = 0; i < NPTS/8; i++) {
            int n = n0 + i;
            float4 qn = sm.c.sQ[n];                       // pre-scaled -2
            unsigned int bb = sm.c.sB[n];
            float va = fmaf(tax, qn.x, qn.w);
            va = fmaf(tay, qn.y, va);
            va = fmaf(taz, qn.z, va);
            float vb = fmaf(tbx, qn.x, qn.w);
            vb = fmaf(tby, qn.y, vb);
            vb = fmaf(tbz, qn.z, vb);
            gmina = fminf(gmina, va);
            gminb = fminf(gminb, vb);
            pmina = fminf(pmina, (bb & maska) ? va : 1e30f);
            pminb = fminf(pminb, (bb & maskb) ? vb : 1e30f);
        }
#pragma unroll
        for (int o = 4; o <= 16; o <<= 1) {
            gmina = fminf(gmina, __shfl_xor_sync(0xffffffffu, gmina, o));
            gminb = fminf(gminb, __shfl_xor_sync(0xffffffffu, gminb, o));
            pmina = fminf(pmina, __shfl_xor_sync(0xffffffffu, pmina, o));
            pminb = fminf(pminb, __shfl_xor_sync(0xffffffffu, pminb, o));
        }
        if (oct == 0) {
            atomicAdd(&sm.c.scham, sqrtf(fmaxf(gmina + tan2, 0.f)));
            float dj = sqrtf(fmaxf(pmina + tan2, 0.f));
            if (dj < 10.f) atomicAdd(&sm.c.sj[pa], dj);
        }
        if (oct == 1) {
            atomicAdd(&sm.c.scham, sqrtf(fmaxf(gminb + tbn2, 0.f)));
            float dj = sqrtf(fmaxf(pminb + tbn2, 0.f));
            if (dj < 10.f) atomicAdd(&sm.c.sj[pb], dj);
        }
        __syncthreads();
        if (t < NJ) atomicAdd(&g_j2[t], sm.c.sj[t]);
        if (t == 0) atomicAdd(&g_cham2, sm.c.scham);
    }
}

// ---- K4: finalize ----
__global__ void k_final(const float* __restrict__ cp, const float* __restrict__ qt,
                        const float* __restrict__ tc, float* __restrict__ out) {
    __shared__ float s_coord, s_p;
    int t = threadIdx.x;
    if (t == 0) { s_coord = 0.f; s_p = 0.f; }
    __syncthreads();

    float ca = 0.f;
    for (int i = t; i < BATCH*NJ*3; i += blockDim.x) {
        float d = cp[i] - tc[i];
        ca += d * d;
    }
    float pa = 0.f;
    for (int i = t; i < BATCH*NJ; i += blockDim.x) {
        int j = i % NJ;
        float w = qt[4*i], x = qt[4*i+1], y = qt[4*i+2], z = qt[4*i+3];
        float inv = 1.0f / sqrtf(w*w + x*x + y*y + z*z);
        w *= inv; x *= inv; y *= inv; z *= inv;
        float a0 = atan2f(2.f*(w*x + y*z), 1.f - 2.f*(x*x + y*y));
        float a1 = asinf(fminf(fmaxf(2.f*(w*y - z*x), -1.f), 1.f));
        float a2 = atan2f(2.f*(w*z + x*y), 1.f - 2.f*(y*y + z*z));
        float a[3] = {a0, a1, a2};
#pragma unroll
        for (int c = 0; c < 3; c++) {
            float lo = c_ranges[j*6 + c*2], hi = c_ranges[j*6 + c*2 + 1];
            pa += fmaxf(lo - a[c], 0.f) + fmaxf(a[c] - hi, 0.f);
        }
    }
    atomicAdd(&s_coord, ca);
    atomicAdd(&s_p, pa);
    __syncthreads();
    if (t == 0) {
        float coord = s_coord / (float)(BATCH*NJ*3);
        float pl    = s_p / (float)(BATCH*NJ);
        float cham  = (g_cham1 + g_cham2) / (float)TOTAL;
        float jm = 0.f;
        for (int i = 0; i < NJ; i++) {
            float jl = (g_j1[i] + g_j2[i]) / (float)TOTAL;
            out[2 + i] = jl;
            jm += jl;
        }
        jm /= (float)NJ;
        out[0]  = 0.1f*cham + 0.1f*jm + coord + 0.1f*pl;
        out[1]  = coord;
        out[23] = cham;
        out[24] = pl;
    }
}

// ---------------- launch ----------------
extern "C" void kernel_launch(void* const* d_in, const int* in_sizes, int n_in,
                              void* d_out, int out_size) {
    const float* gen_pc      = (const float*)d_in[0];
    const int*   out_idxs    = (const int*)  d_in[1];
    const float* coords_pred = (const float*)d_in[2];
    const float* quats       = (const float*)d_in[3];
    const float* seg_logits  = (const float*)d_in[4];
    const float* bone_w      = (const float*)d_in[5];
    const float* tcoords     = (const float*)d_in[6];
    const float* target_pc   = (const float*)d_in[7];
    float* out = (float*)d_out;

    k_pack_label <<<TOTAL/256, 256>>>(gen_pc, out_idxs, seg_logits, bone_w);
    k_sort       <<<BATCH, 512>>>(target_pc);
    k_main       <<<512, 256>>>(target_pc);
    k_final      <<<1, 256>>>(coords_pred, quats, tcoords, out);
}

// round 14
// speedup vs baseline: 1.2914x; 1.2914x over previous
#include <cuda_runtime.h>
#include <math.h>

#define BATCH 8
#define NPTS  2048
#define NJ    21
#define NWGT  778
#define TOTAL (BATCH*NPTS)

// ---------------- device scratch ----------------
__device__ float4 g_q4[TOTAL];          // gen RAW: x,y,z,|q|^2
__device__ unsigned int g_qbits[TOTAL]; // gen joint-mask bits
__device__ int    g_label[TOTAL];       // argmin segment label per (b,m)
__device__ float4 g_tsorted[TOTAL];     // target sorted by label, SCALED: -2x,-2y,-2z,|t|^2
__device__ int    g_offs[BATCH*(NJ+1)];
__device__ float  g_cham1, g_cham2;
__device__ float  g_j1[NJ], g_j2[NJ];
__device__ float  g_coord_sum, g_p_sum;
__device__ int    g_done;

__constant__ float c_ranges[NJ*6] = {
  -1.57f,1.57f, -1.57f,1.57f, -1.57f,1.57f,
  -1.05f,1.05f, 0.f,0.f, -0.79f,0.26f,
  -0.52f,0.52f, 0.f,0.f, -0.35f,0.79f,
  -0.26f,0.26f, 0.f,0.f, 0.f,0.f,
  -1.05f,0.f,   0.f,0.f, 0.f,0.f,
   0.f,0.f,     0.f,0.f, 0.f,0.f,
  -1.05f,0.26f, 0.f,0.f, -0.52f,0.26f,
  -0.52f,0.f,   0.f,0.f, 0.f,0.f,
  -0.52f,0.f,   0.f,0.f, 0.f,0.f,
   0.f,0.f,     0.f,0.f, 0.f,0.f,
  -1.05f,0.26f, 0.f,0.f, -0.52f,0.26f,
  -0.52f,0.f,   0.f,0.f, 0.f,0.f,
  -0.52f,0.f,   0.f,0.f, 0.f,0.f,
   0.f,0.f,     0.f,0.f, 0.f,0.f,
  -1.05f,0.26f, 0.f,0.f, -0.52f,0.26f,
  -0.52f,0.f,   0.f,0.f, 0.f,0.f,
  -0.52f,0.f,   0.f,0.f, 0.f,0.f,
   0.f,0.f,     0.f,0.f, 0.f,0.f,
  -1.05f,0.26f, 0.f,0.f, -0.52f,0.26f,
  -0.52f,0.f,   0.f,0.f, 0.f,0.f,
  -0.52f,0.f,   0.f,0.f, 0.f,0.f
};

// fast atan2 (Hastings poly, ~1e-5 rad abs error)
__device__ __forceinline__ float fatan2(float y, float x) {
    float ax = fabsf(x), ay = fabsf(y);
    float mn = fminf(ax, ay), mx = fmaxf(ax, ay);
    float t = __fdividef(mn, mx);
    float s = t * t;
    float r = fmaf(fmaf(fmaf(fmaf(0.0208351f, s, -0.0851330f), s, 0.1801410f),
                        s, -0.3302995f), s, 0.9998660f) * t;
    if (ay > ax) r = 1.5707963268f - r;
    if (x < 0.f) r = 3.1415926536f - r;
    return copysignf(r, y);
}
__device__ __forceinline__ float fasin(float v) {
    return fatan2(v, sqrtf(fmaxf(1.f - v*v, 0.f)));
}

// ---- K1: pack gen (norm + bits) + labels; block 0 also zeroes accumulators ----
__global__ void __launch_bounds__(256) k_pack_label(
        const float* __restrict__ gen, const int* __restrict__ idxs,
        const float* __restrict__ seg, const float* __restrict__ bw) {
    __shared__ float sl[256*NJ];
    __shared__ unsigned int swb[NWGT];
    int t = threadIdx.x, blk = blockIdx.x;
    int gid = blk*256 + t;
    if (blk == 0) {
        if (t < NJ) { g_j1[t] = 0.f; g_j2[t] = 0.f; }
        if (t == 0) { g_cham1 = 0.f; g_cham2 = 0.f;
                      g_coord_sum = 0.f; g_p_sum = 0.f; g_done = 0; }
    }
    for (int v = t; v < NWGT; v += 256) {
        unsigned int bits = 0;
#pragma unroll
        for (int i = 0; i < NJ; i++)
            bits |= (bw[i*NWGT + v] > 0.15f) ? (1u << i) : 0u;
        swb[v] = bits;
    }
    const float* segb = seg + (size_t)blk*256*NJ;
    for (int i = t; i < 256*NJ; i += 256) sl[i] = segb[i];
    float x = gen[3*gid], y = gen[3*gid+1], z = gen[3*gid+2];
    float4 q; q.x = x; q.y = y; q.z = z; q.w = x*x + y*y + z*z;
    g_q4[gid] = q;
    __syncthreads();
    g_qbits[gid] = swb[idxs[gid]];
    const float* s = &sl[t*NJ];
    float best = s[0]; int bi = 0;
#pragma unroll
    for (int k = 1; k < NJ; k++) {
        float v = s[k];
        if (v < best) { best = v; bi = k; }
    }
    g_label[gid] = bi;
}

// ---- K2: blocks 0-7 counting sort; block 8 coord MSE; block 9 physical loss ----
__global__ void __launch_bounds__(512) k_sort(const float* __restrict__ tpc,
                                              const float* __restrict__ cp,
                                              const float* __restrict__ tc,
                                              const float* __restrict__ qt) {
    int t = threadIdx.x, b = blockIdx.x;
    if (b == 8) {
        // coordinate MSE partial sum
        float ca = 0.f;
        if (t < BATCH*NJ*3) {
            float d = cp[t] - tc[t];
            ca = d * d;
        }
#pragma unroll
        for (int o = 16; o > 0; o >>= 1) ca += __shfl_xor_sync(0xffffffffu, ca, o);
        if ((t & 31) == 0 && ca != 0.f) atomicAdd(&g_coord_sum, ca);
        return;
    }
    if (b == 9) {
        // physical (Euler range) partial sum
        float pa = 0.f;
        if (t < BATCH*NJ) {
            int j = t % NJ;
            float w = qt[4*t], x = qt[4*t+1], y = qt[4*t+2], z = qt[4*t+3];
            float inv = rsqrtf(w*w + x*x + y*y + z*z);
            w *= inv; x *= inv; y *= inv; z *= inv;
            float a0 = fatan2(2.f*(w*x + y*z), 1.f - 2.f*(x*x + y*y));
            float a1 = fasin(fminf(fmaxf(2.f*(w*y - z*x), -1.f), 1.f));
            float a2 = fatan2(2.f*(w*z + x*y), 1.f - 2.f*(y*y + z*z));
            float a[3] = {a0, a1, a2};
#pragma unroll
            for (int c = 0; c < 3; c++) {
                float lo = c_ranges[j*6 + c*2], hi = c_ranges[j*6 + c*2 + 1];
                pa += fmaxf(lo - a[c], 0.f) + fmaxf(a[c] - hi, 0.f);
            }
        }
#pragma unroll
        for (int o = 16; o > 0; o >>= 1) pa += __shfl_xor_sync(0xffffffffu, pa, o);
        if ((t & 31) == 0 && pa != 0.f) atomicAdd(&g_p_sum, pa);
        return;
    }
    __shared__ int hist[NJ];
    __shared__ int cur[NJ];
    __shared__ int labs[NPTS];
    if (t < NJ) hist[t] = 0;
    __syncthreads();
    int base = b << 11;
#pragma unroll
    for (int k = 0; k < 4; k++) {
        int i = t + 512*k;
        int lab = g_label[base + i];
        labs[i] = lab;
        atomicAdd(&hist[lab], 1);
    }
    __syncthreads();
    if (t == 0) {
        int run = 0;
        for (int j = 0; j < NJ; j++) {
            g_offs[b*(NJ+1) + j] = run;
            cur[j] = run;
            run += hist[j];
        }
        g_offs[b*(NJ+1) + NJ] = run;
    }
    __syncthreads();
#pragma unroll
    for (int k = 0; k < 4; k++) {
        int i = t + 512*k;
        int lab = labs[i];
        int pos = atomicAdd(&cur[lab], 1);
        int gi = base + i;
        float x = tpc[3*gi], y = tpc[3*gi+1], z = tpc[3*gi+2];
        float4 v;
        v.x = -2.f*x; v.y = -2.f*y; v.z = -2.f*z;
        v.w = x*x + y*y + z*z;
        g_tsorted[base + pos] = v;
    }
}

// ---- K3: FUSED main pass (128 thr, 1024 blocks). [0,512): row; [512,1024): col.
// Last-finishing block combines everything into out (ticket pattern).
struct RowS { float4 sT[NPTS]; int soff[NJ+1]; float sj[NJ]; float scham; };
struct ColS { float4 sQ[NPTS]; unsigned int sB[NPTS]; float sj[NJ]; float scham; };
union MainS { RowS r; ColS c; };

__global__ void __launch_bounds__(128) k_main(const float* __restrict__ tpc,
                                              float* __restrict__ out) {
    __shared__ MainS sm;
    __shared__ int sticket;
    int t = threadIdx.x;
    int warp = t >> 5, lane = t & 31;
    int oct = lane >> 2, ql = lane & 3;

    if (blockIdx.x < 512) {
        // ================= ROW =================
        int b = blockIdx.x >> 6;            // 64 blocks per batch
        int qblk = blockIdx.x & 63;         // 32 queries per block
        for (int i = t; i < NPTS; i += 128) sm.r.sT[i] = g_tsorted[(b << 11) + i];
        if (t < NJ+1) sm.r.soff[t] = g_offs[b*(NJ+1) + t];
        if (t < NJ) sm.r.sj[t] = 0.f;
        if (t == 0) sm.r.scham = 0.f;
        __syncthreads();

        int qbase = (b << 11) + qblk*32 + warp*8;
        float4 qa = g_q4[qbase + ql];
        float4 qb = g_q4[qbase + 4 + ql];
        unsigned int bits_a = g_qbits[qbase + ql];
        unsigned int bits_b = g_qbits[qbase + 4 + ql];
        float gmall_a = 1e30f, gmall_b = 1e30f;

        for (int grp = 0; grp < NJ; grp++) {
            int s = sm.r.soff[grp], e = sm.r.soff[grp+1];
            int hlen = (e - s + 7) >> 3;
            int m0 = s + oct*hlen;
            int mend = min(m0 + hlen, e);
            float gma = 1e30f, gmb = 1e30f;
#pragma unroll 4
            for (int m = m0; m < mend; m++) {
                float4 tp = sm.r.sT[m];                   // pre-scaled -2
                float va = fmaf(qa.x, tp.x, tp.w);
                va = fmaf(qa.y, tp.y, va);
                va = fmaf(qa.z, tp.z, va);
                float vb = fmaf(qb.x, tp.x, tp.w);
                vb = fmaf(qb.y, tp.y, vb);
                vb = fmaf(qb.z, tp.z, vb);
                gma = fminf(gma, va);
                gmb = fminf(gmb, vb);
            }
            gma = fminf(gma, __shfl_xor_sync(0xffffffffu, gma, 4));
            gma = fminf(gma, __shfl_xor_sync(0xffffffffu, gma, 8));
            gma = fminf(gma, __shfl_xor_sync(0xffffffffu, gma, 16));
            gmb = fminf(gmb, __shfl_xor_sync(0xffffffffu, gmb, 4));
            gmb = fminf(gmb, __shfl_xor_sync(0xffffffffu, gmb, 8));
            gmb = fminf(gmb, __shfl_xor_sync(0xffffffffu, gmb, 16));
            gmall_a = fminf(gmall_a, gma);
            gmall_b = fminf(gmall_b, gmb);
            if (oct == 0 && ((bits_a >> grp) & 1u)) {
                float d = sqrtf(fmaxf(gma + qa.w, 0.f));
                if (d < 10.f) atomicAdd(&sm.r.sj[grp], d);
            }
            if (oct == 1 && ((bits_b >> grp) & 1u)) {
                float d = sqrtf(fmaxf(gmb + qb.w, 0.f));
                if (d < 10.f) atomicAdd(&sm.r.sj[grp], d);
            }
        }
        if (oct == 0) atomicAdd(&sm.r.scham, sqrtf(fmaxf(gmall_a + qa.w, 0.f)));
        if (oct == 1) atomicAdd(&sm.r.scham, sqrtf(fmaxf(gmall_b + qb.w, 0.f)));
        __syncthreads();
        if (t < NJ) atomicAdd(&g_j1[t], sm.r.sj[t]);
        if (t == 0) atomicAdd(&g_cham1, sm.r.scham);
    } else {
        // ================= COL =================
        int blk = blockIdx.x - 512;
        int b = blk >> 6;
        int mblk = blk & 63;
        for (int i = t; i < NPTS; i += 128) {
            float4 v = g_q4[(b << 11) + i];
            v.x *= -2.f; v.y *= -2.f; v.z *= -2.f;    // scale into tile
            sm.c.sQ[i] = v;
            sm.c.sB[i] = g_qbits[(b << 11) + i];
        }
        if (t < NJ) sm.c.sj[t] = 0.f;
        if (t == 0) sm.c.scham = 0.f;
        __syncthreads();

        int mbase = (b << 11) + mblk*32 + warp*8;
        int gia = mbase + ql, gib = mbase + 4 + ql;
        float tax = tpc[3*gia], tay = tpc[3*gia+1], taz = tpc[3*gia+2];
        float tbx = tpc[3*gib], tby = tpc[3*gib+1], tbz = tpc[3*gib+2];
        float tan2 = tax*tax + tay*tay + taz*taz;
        float tbn2 = tbx*tbx + tby*tby + tbz*tbz;
        int pa = g_label[gia], pb = g_label[gib];
        unsigned int maska = 1u << pa, maskb = 1u << pb;
        float gmina = 1e30f, gminb = 1e30f, pmina = 1e30f, pminb = 1e30f;
        int n0 = oct * (NPTS/8);

#pragma unroll 4
        for (int i = 0; i < NPTS/8; i++) {
            int n = n0 + i;
            float4 qn = sm.c.sQ[n];                       // pre-scaled -2
            unsigned int bb = sm.c.sB[n];
            float va = fmaf(tax, qn.x, qn.w);
            va = fmaf(tay, qn.y, va);
            va = fmaf(taz, qn.z, va);
            float vb = fmaf(tbx, qn.x, qn.w);
            vb = fmaf(tby, qn.y, vb);
            vb = fmaf(tbz, qn.z, vb);
            gmina = fminf(gmina, va);
            gminb = fminf(gminb, vb);
            pmina = fminf(pmina, (bb & maska) ? va : 1e30f);
            pminb = fminf(pminb, (bb & maskb) ? vb : 1e30f);
        }
#pragma unroll
        for (int o = 4; o <= 16; o <<= 1) {
            gmina = fminf(gmina, __shfl_xor_sync(0xffffffffu, gmina, o));
            gminb = fminf(gminb, __shfl_xor_sync(0xffffffffu, gminb, o));
            pmina = fminf(pmina, __shfl_xor_sync(0xffffffffu, pmina, o));
            pminb = fminf(pminb, __shfl_xor_sync(0xffffffffu, pminb, o));
        }
        if (oct == 0) {
            atomicAdd(&sm.c.scham, sqrtf(fmaxf(gmina + tan2, 0.f)));
            float dj = sqrtf(fmaxf(pmina + tan2, 0.f));
            if (dj < 10.f) atomicAdd(&sm.c.sj[pa], dj);
        }
        if (oct == 1) {
            atomicAdd(&sm.c.scham, sqrtf(fmaxf(gminb + tbn2, 0.f)));
            float dj = sqrtf(fmaxf(pminb + tbn2, 0.f));
            if (dj < 10.f) atomicAdd(&sm.c.sj[pb], dj);
        }
        __syncthreads();
        if (t < NJ) atomicAdd(&g_j2[t], sm.c.sj[t]);
        if (t == 0) atomicAdd(&g_cham2, sm.c.scham);
    }

    // ---- last-block combine (threadFenceReduction pattern) ----
    __threadfence();
    __syncthreads();
    if (t == 0) sticket = atomicAdd(&g_done, 1);
    __syncthreads();
    if (sticket == 1023 && t == 0) {
        float coord = g_coord_sum / (float)(BATCH*NJ*3);
        float pl    = g_p_sum / (float)(BATCH*NJ);
        float cham  = (g_cham1 + g_cham2) / (float)TOTAL;
        float jm = 0.f;
        for (int i = 0; i < NJ; i++) {
            float jl = (g_j1[i] + g_j2[i]) / (float)TOTAL;
            out[2 + i] = jl;
            jm += jl;
        }
        jm /= (float)NJ;
        out[0]  = 0.1f*cham + 0.1f*jm + coord + 0.1f*pl;
        out[1]  = coord;
        out[23] = cham;
        out[24] = pl;
    }
}

// ---------------- launch ----------------
extern "C" void kernel_launch(void* const* d_in, const int* in_sizes, int n_in,
                              void* d_out, int out_size) {
    const float* gen_pc      = (const float*)d_in[0];
    const int*   out_idxs    = (const int*)  d_in[1];
    const float* coords_pred = (const float*)d_in[2];
    const float* quats       = (const float*)d_in[3];
    const float* seg_logits  = (const float*)d_in[4];
    const float* bone_w      = (const float*)d_in[5];
    const float* tcoords     = (const float*)d_in[6];
    const float* target_pc   = (const float*)d_in[7];
    float* out = (float*)d_out;

    k_pack_label <<<TOTAL/256, 256>>>(gen_pc, out_idxs, seg_logits, bone_w);
    k_sort       <<<BATCH+2, 512>>>(target_pc, coords_pred, tcoords, quats);
    k_main       <<<1024, 128>>>(target_pc, out);
}

// round 15
// speedup vs baseline: 1.3394x; 1.0372x over previous
#include <cuda_runtime.h>
#include <math.h>

#define BATCH 8
#define NPTS  2048
#define NJ    21
#define NWGT  778
#define TOTAL (BATCH*NPTS)

// ---------------- device scratch ----------------
__device__ float4 g_q4[TOTAL];          // gen RAW: x,y,z,|q|^2
__device__ unsigned int g_qbits[TOTAL]; // gen joint-mask bits
__device__ int    g_label[TOTAL];       // argmin segment label per (b,m)
__device__ float4 g_tsorted[TOTAL];     // target sorted by label, SCALED: -2x,-2y,-2z,|t|^2
__device__ int    g_offs[BATCH*(NJ+1)];
__device__ float  g_cham1, g_cham2;
__device__ float  g_j1[NJ], g_j2[NJ];
__device__ float  g_coord_sum, g_p_sum;
__device__ int    g_done;

__constant__ float c_ranges[NJ*6] = {
  -1.57f,1.57f, -1.57f,1.57f, -1.57f,1.57f,
  -1.05f,1.05f, 0.f,0.f, -0.79f,0.26f,
  -0.52f,0.52f, 0.f,0.f, -0.35f,0.79f,
  -0.26f,0.26f, 0.f,0.f, 0.f,0.f,
  -1.05f,0.f,   0.f,0.f, 0.f,0.f,
   0.f,0.f,     0.f,0.f, 0.f,0.f,
  -1.05f,0.26f, 0.f,0.f, -0.52f,0.26f,
  -0.52f,0.f,   0.f,0.f, 0.f,0.f,
  -0.52f,0.f,   0.f,0.f, 0.f,0.f,
   0.f,0.f,     0.f,0.f, 0.f,0.f,
  -1.05f,0.26f, 0.f,0.f, -0.52f,0.26f,
  -0.52f,0.f,   0.f,0.f, 0.f,0.f,
  -0.52f,0.f,   0.f,0.f, 0.f,0.f,
   0.f,0.f,     0.f,0.f, 0.f,0.f,
  -1.05f,0.26f, 0.f,0.f, -0.52f,0.26f,
  -0.52f,0.f,   0.f,0.f, 0.f,0.f,
  -0.52f,0.f,   0.f,0.f, 0.f,0.f,
   0.f,0.f,     0.f,0.f, 0.f,0.f,
  -1.05f,0.26f, 0.f,0.f, -0.52f,0.26f,
  -0.52f,0.f,   0.f,0.f, 0.f,0.f,
  -0.52f,0.f,   0.f,0.f, 0.f,0.f
};

// fast atan2 (Hastings poly, ~1e-5 rad abs error)
__device__ __forceinline__ float fatan2(float y, float x) {
    float ax = fabsf(x), ay = fabsf(y);
    float mn = fminf(ax, ay), mx = fmaxf(ax, ay);
    float t = __fdividef(mn, mx);
    float s = t * t;
    float r = fmaf(fmaf(fmaf(fmaf(0.0208351f, s, -0.0851330f), s, 0.1801410f),
                        s, -0.3302995f), s, 0.9998660f) * t;
    if (ay > ax) r = 1.5707963268f - r;
    if (x < 0.f) r = 3.1415926536f - r;
    return copysignf(r, y);
}
__device__ __forceinline__ float fasin(float v) {
    return fatan2(v, sqrtf(fmaxf(1.f - v*v, 0.f)));
}

// ---- K1: labels + gen pack ONLY. grid 256 x 128, 64 points per block. ----
__global__ void __launch_bounds__(128) k_pack_label(
        const float* __restrict__ gen, const float* __restrict__ seg) {
    __shared__ float sl[64*NJ];
    int t = threadIdx.x, blk = blockIdx.x;
    if (blk == 0) {
        if (t < NJ) { g_j1[t] = 0.f; g_j2[t] = 0.f; }
        if (t == 0) { g_cham1 = 0.f; g_cham2 = 0.f;
                      g_coord_sum = 0.f; g_p_sum = 0.f; g_done = 0; }
    }
    const float* segb = seg + (size_t)blk*64*NJ;
    for (int i = t; i < 64*NJ; i += 128) sl[i] = segb[i];
    __syncthreads();
    if (t < 64) {
        int gid = blk*64 + t;
        float x = gen[3*gid], y = gen[3*gid+1], z = gen[3*gid+2];
        float4 q; q.x = x; q.y = y; q.z = z; q.w = x*x + y*y + z*z;
        g_q4[gid] = q;
        const float* s = &sl[t*NJ];
        float best = s[0]; int bi = 0;
#pragma unroll
        for (int k = 1; k < NJ; k++) {
            float v = s[k];
            if (v < best) { best = v; bi = k; }
        }
        g_label[gid] = bi;
    }
}

// ---- K2: blocks 0-7 sort; 8 coord MSE; 9 physical; 10-17 wbits+qbits gather ----
__global__ void __launch_bounds__(512) k_sort(const float* __restrict__ tpc,
                                              const float* __restrict__ cp,
                                              const float* __restrict__ tc,
                                              const float* __restrict__ qt,
                                              const float* __restrict__ bw,
                                              const int* __restrict__ idxs) {
    int t = threadIdx.x, b = blockIdx.x;
    if (b == 8) {
        float ca = 0.f;
        if (t < BATCH*NJ*3) {
            float d = cp[t] - tc[t];
            ca = d * d;
        }
#pragma unroll
        for (int o = 16; o > 0; o >>= 1) ca += __shfl_xor_sync(0xffffffffu, ca, o);
        if ((t & 31) == 0 && ca != 0.f) atomicAdd(&g_coord_sum, ca);
        return;
    }
    if (b == 9) {
        float pa = 0.f;
        if (t < BATCH*NJ) {
            int j = t % NJ;
            float w = qt[4*t], x = qt[4*t+1], y = qt[4*t+2], z = qt[4*t+3];
            float inv = rsqrtf(w*w + x*x + y*y + z*z);
            w *= inv; x *= inv; y *= inv; z *= inv;
            float a0 = fatan2(2.f*(w*x + y*z), 1.f - 2.f*(x*x + y*y));
            float a1 = fasin(fminf(fmaxf(2.f*(w*y - z*x), -1.f), 1.f));
            float a2 = fatan2(2.f*(w*z + x*y), 1.f - 2.f*(y*y + z*z));
            float a[3] = {a0, a1, a2};
#pragma unroll
            for (int c = 0; c < 3; c++) {
                float lo = c_ranges[j*6 + c*2], hi = c_ranges[j*6 + c*2 + 1];
                pa += fmaxf(lo - a[c], 0.f) + fmaxf(a[c] - hi, 0.f);
            }
        }
#pragma unroll
        for (int o = 16; o > 0; o >>= 1) pa += __shfl_xor_sync(0xffffffffu, pa, o);
        if ((t & 31) == 0 && pa != 0.f) atomicAdd(&g_p_sum, pa);
        return;
    }
    if (b >= 10) {
        // wbits (per-block smem table) + qbits gather for one batch
        __shared__ unsigned int swb[NWGT];
        for (int v = t; v < NWGT; v += 512) {
            unsigned int bits = 0;
#pragma unroll
            for (int i = 0; i < NJ; i++)
                bits |= (bw[i*NWGT + v] > 0.15f) ? (1u << i) : 0u;
            swb[v] = bits;
        }
        __syncthreads();
        int base = (b - 10) << 11;
#pragma unroll
        for (int k = 0; k < 4; k++) {
            int i = base + t + 512*k;
            g_qbits[i] = swb[idxs[i]];
        }
        return;
    }
    __shared__ int hist[NJ];
    __shared__ int cur[NJ];
    __shared__ int labs[NPTS];
    if (t < NJ) hist[t] = 0;
    __syncthreads();
    int base = b << 11;
#pragma unroll
    for (int k = 0; k < 4; k++) {
        int i = t + 512*k;
        int lab = g_label[base + i];
        labs[i] = lab;
        atomicAdd(&hist[lab], 1);
    }
    __syncthreads();
    if (t == 0) {
        int run = 0;
        for (int j = 0; j < NJ; j++) {
            g_offs[b*(NJ+1) + j] = run;
            cur[j] = run;
            run += hist[j];
        }
        g_offs[b*(NJ+1) + NJ] = run;
    }
    __syncthreads();
#pragma unroll
    for (int k = 0; k < 4; k++) {
        int i = t + 512*k;
        int lab = labs[i];
        int pos = atomicAdd(&cur[lab], 1);
        int gi = base + i;
        float x = tpc[3*gi], y = tpc[3*gi+1], z = tpc[3*gi+2];
        float4 v;
        v.x = -2.f*x; v.y = -2.f*y; v.z = -2.f*z;
        v.w = x*x + y*y + z*z;
        g_tsorted[base + pos] = v;
    }
}

// ---- K3: FUSED main pass (128 thr, 1024 blocks). [0,512): row; [512,1024): col.
// Last-finishing block combines everything into out (ticket pattern).
struct RowS { float4 sT[NPTS]; int soff[NJ+1]; float sj[NJ]; float scham; };
struct ColS { float4 sQ[NPTS]; unsigned int sB[NPTS]; float sj[NJ]; float scham; };
union MainS { RowS r; ColS c; };

__global__ void __launch_bounds__(128) k_main(const float* __restrict__ tpc,
                                              float* __restrict__ out) {
    __shared__ MainS sm;
    __shared__ int sticket;
    int t = threadIdx.x;
    int warp = t >> 5, lane = t & 31;
    int oct = lane >> 2, ql = lane & 3;

    if (blockIdx.x < 512) {
        // ================= ROW =================
        int b = blockIdx.x >> 6;            // 64 blocks per batch
        int qblk = blockIdx.x & 63;         // 32 queries per block
        for (int i = t; i < NPTS; i += 128) sm.r.sT[i] = g_tsorted[(b << 11) + i];
        if (t < NJ+1) sm.r.soff[t] = g_offs[b*(NJ+1) + t];
        if (t < NJ) sm.r.sj[t] = 0.f;
        if (t == 0) sm.r.scham = 0.f;
        __syncthreads();

        int qbase = (b << 11) + qblk*32 + warp*8;
        float4 qa = g_q4[qbase + ql];
        float4 qb = g_q4[qbase + 4 + ql];
        unsigned int bits_a = g_qbits[qbase + ql];
        unsigned int bits_b = g_qbits[qbase + 4 + ql];
        float gmall_a = 1e30f, gmall_b = 1e30f;

        for (int grp = 0; grp < NJ; grp++) {
            int s = sm.r.soff[grp], e = sm.r.soff[grp+1];
            int hlen = (e - s + 7) >> 3;
            int m0 = s + oct*hlen;
            int mend = min(m0 + hlen, e);
            float gma = 1e30f, gmb = 1e30f;
#pragma unroll 4
            for (int m = m0; m < mend; m++) {
                float4 tp = sm.r.sT[m];                   // pre-scaled -2
                float va = fmaf(qa.x, tp.x, tp.w);
                va = fmaf(qa.y, tp.y, va);
                va = fmaf(qa.z, tp.z, va);
                float vb = fmaf(qb.x, tp.x, tp.w);
                vb = fmaf(qb.y, tp.y, vb);
                vb = fmaf(qb.z, tp.z, vb);
                gma = fminf(gma, va);
                gmb = fminf(gmb, vb);
            }
            gma = fminf(gma, __shfl_xor_sync(0xffffffffu, gma, 4));
            gma = fminf(gma, __shfl_xor_sync(0xffffffffu, gma, 8));
            gma = fminf(gma, __shfl_xor_sync(0xffffffffu, gma, 16));
            gmb = fminf(gmb, __shfl_xor_sync(0xffffffffu, gmb, 4));
            gmb = fminf(gmb, __shfl_xor_sync(0xffffffffu, gmb, 8));
            gmb = fminf(gmb, __shfl_xor_sync(0xffffffffu, gmb, 16));
            gmall_a = fminf(gmall_a, gma);
            gmall_b = fminf(gmall_b, gmb);
            if (oct == 0 && ((bits_a >> grp) & 1u)) {
                float d = sqrtf(fmaxf(gma + qa.w, 0.f));
                if (d < 10.f) atomicAdd(&sm.r.sj[grp], d);
            }
            if (oct == 1 && ((bits_b >> grp) & 1u)) {
                float d = sqrtf(fmaxf(gmb + qb.w, 0.f));
                if (d < 10.f) atomicAdd(&sm.r.sj[grp], d);
            }
        }
        if (oct == 0) atomicAdd(&sm.r.scham, sqrtf(fmaxf(gmall_a + qa.w, 0.f)));
        if (oct == 1) atomicAdd(&sm.r.scham, sqrtf(fmaxf(gmall_b + qb.w, 0.f)));
        __syncthreads();
        if (t < NJ) atomicAdd(&g_j1[t], sm.r.sj[t]);
        if (t == 0) atomicAdd(&g_cham1, sm.r.scham);
    } else {
        // ================= COL =================
        int blk = blockIdx.x - 512;
        int b = blk >> 6;
        int mblk = blk & 63;
        for (int i = t; i < NPTS; i += 128) {
            float4 v = g_q4[(b << 11) + i];
            v.x *= -2.f; v.y *= -2.f; v.z *= -2.f;    // scale into tile
            sm.c.sQ[i] = v;
            sm.c.sB[i] = g_qbits[(b << 11) + i];
        }
        if (t < NJ) sm.c.sj[t] = 0.f;
        if (t == 0) sm.c.scham = 0.f;
        __syncthreads();

        int mbase = (b << 11) + mblk*32 + warp*8;
        int gia = mbase + ql, gib = mbase + 4 + ql;
        float tax = tpc[3*gia], tay = tpc[3*gia+1], taz = tpc[3*gia+2];
        float tbx = tpc[3*gib], tby = tpc[3*gib+1], tbz = tpc[3*gib+2];
        float tan2 = tax*tax + tay*tay + taz*taz;
        float tbn2 = tbx*tbx + tby*tby + tbz*tbz;
        int pa = g_label[gia], pb = g_label[gib];
        unsigned int maska = 1u << pa, maskb = 1u << pb;
        float gmina = 1e30f, gminb = 1e30f, pmina = 1e30f, pminb = 1e30f;
        int n0 = oct * (NPTS/8);

#pragma unroll 4
        for (int i = 0; i < NPTS/8; i++) {
            int n = n0 + i;
            float4 qn = sm.c.sQ[n];                       // pre-scaled -2
            unsigned int bb = sm.c.sB[n];
            float va = fmaf(tax, qn.x, qn.w);
            va = fmaf(tay, qn.y, va);
            va = fmaf(taz, qn.z, va);
            float vb = fmaf(tbx, qn.x, qn.w);
            vb = fmaf(tby, qn.y, vb);
            vb = fmaf(tbz, qn.z, vb);
            gmina = fminf(gmina, va);
            gminb = fminf(gminb, vb);
            pmina = fminf(pmina, (bb & maska) ? va : 1e30f);
            pminb = fminf(pminb, (bb & maskb) ? vb : 1e30f);
        }
#pragma unroll
        for (int o = 4; o <= 16; o <<= 1) {
            gmina = fminf(gmina, __shfl_xor_sync(0xffffffffu, gmina, o));
            gminb = fminf(gminb, __shfl_xor_sync(0xffffffffu, gminb, o));
            pmina = fminf(pmina, __shfl_xor_sync(0xffffffffu, pmina, o));
            pminb = fminf(pminb, __shfl_xor_sync(0xffffffffu, pminb, o));
        }
        if (oct == 0) {
            atomicAdd(&sm.c.scham, sqrtf(fmaxf(gmina + tan2, 0.f)));
            float dj = sqrtf(fmaxf(pmina + tan2, 0.f));
            if (dj < 10.f) atomicAdd(&sm.c.sj[pa], dj);
        }
        if (oct == 1) {
            atomicAdd(&sm.c.scham, sqrtf(fmaxf(gminb + tbn2, 0.f)));
            float dj = sqrtf(fmaxf(pminb + tbn2, 0.f));
            if (dj < 10.f) atomicAdd(&sm.c.sj[pb], dj);
        }
        __syncthreads();
        if (t < NJ) atomicAdd(&g_j2[t], sm.c.sj[t]);
        if (t == 0) atomicAdd(&g_cham2, sm.c.scham);
    }

    // ---- last-block combine (threadFenceReduction pattern) ----
    __threadfence();
    __syncthreads();
    if (t == 0) sticket = atomicAdd(&g_done, 1);
    __syncthreads();
    if (sticket == 1023 && t == 0) {
        float coord = g_coord_sum / (float)(BATCH*NJ*3);
        float pl    = g_p_sum / (float)(BATCH*NJ);
        float cham  = (g_cham1 + g_cham2) / (float)TOTAL;
        float jm = 0.f;
        for (int i = 0; i < NJ; i++) {
            float jl = (g_j1[i] + g_j2[i]) / (float)TOTAL;
            out[2 + i] = jl;
            jm += jl;
        }
        jm /= (float)NJ;
        out[0]  = 0.1f*cham + 0.1f*jm + coord + 0.1f*pl;
        out[1]  = coord;
        out[23] = cham;
        out[24] = pl;
    }
}

// ---------------- launch ----------------
extern "C" void kernel_launch(void* const* d_in, const int* in_sizes, int n_in,
                              void* d_out, int out_size) {
    const float* gen_pc      = (const float*)d_in[0];
    const int*   out_idxs    = (const int*)  d_in[1];
    const float* coords_pred = (const float*)d_in[2];
    const float* quats       = (const float*)d_in[3];
    const float* seg_logits  = (const float*)d_in[4];
    const float* bone_w      = (const float*)d_in[5];
    const float* tcoords     = (const float*)d_in[6];
    const float* target_pc   = (const float*)d_in[7];
    float* out = (float*)d_out;

    k_pack_label <<<TOTAL/64, 128>>>(gen_pc, seg_logits);
    k_sort       <<<BATCH+10, 512>>>(target_pc, coords_pred, tcoords, quats,
                                     bone_w, out_idxs);
    k_main       <<<1024, 128>>>(target_pc, out);
}